// round 6
// baseline (speedup 1.0000x reference)
#include <cuda_runtime.h>
#include <cuda_fp16.h>
#include <cstdint>

#define DI __device__ __forceinline__

// problem dims
#define CC   2048
#define WWD  96
#define HWP  4608          // 48*96
#define NCOL 384           // 4*96 GEMM columns

// GEMM tiling
#define BM 64
#define BN 48
#define BK 64
#define KITER (CC/BK)      // 32
#define NST 4
#define AST 72             // padded fp16 row stride (64+8) -> conflict-free ldmatrix
#define A_H (BM*AST)       // 4608 halfs
#define B_H (BN*AST)       // 3456 halfs
#define STG (A_H+B_H)      // 8064 halfs / stage
#define SMEM_BYTES (NST*STG*2)   // 64512 B

// device scratch (static; allocation-rule safe)
__device__ __half g_w[(size_t)CC * CC];            // 8.4 MB, L2-resident
__device__ __half g_carry[2][(size_t)NCOL * CC];   // 2 x 1.5 MB ping-pong

// ---------------- PTX helpers (base sm_103 ISA only) ----------------
DI uint32_t smem_u32(const void* p) {
    uint32_t a;
    asm("{ .reg .u64 t; cvta.to.shared.u64 t, %1; cvt.u32.u64 %0, t; }" : "=r"(a) : "l"(p));
    return a;
}
DI void cp16(uint32_t s, const void* g) {
    asm volatile("cp.async.cg.shared.global [%0], [%1], 16;" :: "r"(s), "l"(g) : "memory");
}
DI void cp_commit() { asm volatile("cp.async.commit_group;" ::: "memory"); }
DI void cp_wait2()  { asm volatile("cp.async.wait_group 2;" ::: "memory"); }

DI void ldsm4(uint32_t a, uint32_t* r) {
    asm volatile("ldmatrix.sync.aligned.m8n8.x4.shared.b16 {%0,%1,%2,%3},[%4];"
        : "=r"(r[0]), "=r"(r[1]), "=r"(r[2]), "=r"(r[3]) : "r"(a));
}
DI void mma16816(float* d, const uint32_t* a, uint32_t b0, uint32_t b1) {
    asm volatile(
        "mma.sync.aligned.m16n8k16.row.col.f32.f16.f16.f32 "
        "{%0,%1,%2,%3},{%4,%5,%6,%7},{%8,%9},{%0,%1,%2,%3};"
        : "+f"(d[0]), "+f"(d[1]), "+f"(d[2]), "+f"(d[3])
        : "r"(a[0]), "r"(a[1]), "r"(a[2]), "r"(a[3]), "r"(b0), "r"(b1));
}

// ---------------- step GEMM kernel ----------------
// D[o][j] = sum_c W[o][c] * carry[j][c];  y = relu(D + b[o]) + src;  out = y; carry' = fp16(y)
__global__ void __launch_bounds__(128, 2)
step_kernel(int pin, const float* __restrict__ bias,
            const float* __restrict__ src, float* __restrict__ out, int h)
{
    extern __shared__ __half sm[];
    uint32_t smb = smem_u32(sm);
    const __half* __restrict__ cin = g_carry[pin];
    __half* __restrict__ cout = g_carry[pin ^ 1];

    const int tid = threadIdx.x, lane = tid & 31, warp = tid >> 5;
    const int mtile = blockIdx.x, ntile = blockIdx.y;
    const __half* gA = g_w + (size_t)(mtile * BM) * CC;
    const __half* gB = cin + (size_t)(ntile * BN) * CC;

    // ---- cp.async stage loader: 896 16B-units (A:512, B:384), 7 per thread ----
    auto load_stage = [&](int s, int kc) {
        uint32_t base = smb + (uint32_t)(s * STG) * 2;
        #pragma unroll
        for (int i = 0; i < 7; i++) {
            int u = tid + i * 128;
            int isB = (u >= 512);
            int uu = isB ? u - 512 : u;
            int r = uu >> 3, ku = uu & 7;
            uint32_t soff = (isB ? A_H : 0) + r * AST + ku * 8;
            const __half* g = (isB ? gB : gA) + (size_t)r * CC + kc + ku * 8;
            cp16(base + soff * 2, g);
        }
    };

    #pragma unroll
    for (int s = 0; s < NST - 1; s++) { load_stage(s, s * BK); cp_commit(); }

    // 4 warps: wm = warp (16 rows each), single 48-col N block
    const int wm = warp;
    float acc[6][4];
    #pragma unroll
    for (int ni = 0; ni < 6; ni++)
        #pragma unroll
        for (int e = 0; e < 4; e++) acc[ni][e] = 0.f;

    const int lr = lane & 15;
    const int lh = (lane >> 4) * 8;
    const uint32_t aoff  = (uint32_t)((wm * 16 + lr) * AST + lh) * 2;
    const uint32_t boff0 = (uint32_t)(A_H + lr * AST + lh) * 2;

    #pragma unroll 1
    for (int it = 0; it < KITER; it++) {
        cp_wait2();
        __syncthreads();
        if (it + NST - 1 < KITER) load_stage((it + NST - 1) & (NST - 1), (it + NST - 1) * BK);
        cp_commit();

        uint32_t base = smb + (uint32_t)((it & (NST - 1)) * STG) * 2;
        uint32_t a[2][4], b[2][3][4];
        ldsm4(base + aoff, a[0]);
        #pragma unroll
        for (int nb = 0; nb < 3; nb++)
            ldsm4(base + boff0 + (uint32_t)(nb * 16 * AST) * 2, b[0][nb]);

        #pragma unroll
        for (int kk = 0; kk < BK / 16; kk++) {
            int cur = kk & 1, nxt = cur ^ 1;
            if (kk + 1 < BK / 16) {
                uint32_t ko = (uint32_t)((kk + 1) * 16) * 2;
                ldsm4(base + aoff + ko, a[nxt]);
                #pragma unroll
                for (int nb = 0; nb < 3; nb++)
                    ldsm4(base + boff0 + (uint32_t)(nb * 16 * AST) * 2 + ko, b[nxt][nb]);
            }
            #pragma unroll
            for (int nb = 0; nb < 3; nb++) {
                mma16816(acc[2 * nb],     a[cur], b[cur][nb][0], b[cur][nb][2]);
                mma16816(acc[2 * nb + 1], a[cur], b[cur][nb][1], b[cur][nb][3]);
            }
        }
    }

    // ---- epilogue ----
    const int g = lane >> 2, cp2 = (lane & 3) * 2;
    const int o0 = mtile * BM + wm * 16;
    float bv0 = bias[o0 + g], bv1 = bias[o0 + g + 8];
    #pragma unroll
    for (int ni = 0; ni < 6; ni++)
        #pragma unroll
        for (int e = 0; e < 4; e++) {
            int o = o0 + g + (e >> 1) * 8;
            int j = ntile * BN + ni * 8 + cp2 + (e & 1);   // global column 0..383
            int n = j / WWD, w = j - n * WWD;
            size_t idx = (size_t)(n * CC + o) * HWP + (size_t)h * WWD + w;
            float v = acc[ni][e] + ((e >> 1) ? bv1 : bv0);
            v = fmaxf(v, 0.f) + src[idx];
            out[idx] = v;
            cout[(size_t)j * CC + o] = __float2half(v);
        }
}

// ---------------- prep kernels ----------------
__global__ void wprep(const float* __restrict__ W) {
    int i = blockIdx.x * 256 + threadIdx.x;
    if (i >= CC * CC) return;
    g_w[i] = __float2half(W[(size_t)i * 9 + 4]);   // center tap of KH=9
}

__global__ void initk(const float* __restrict__ fea, float* __restrict__ out) {
    int i = blockIdx.x * 256 + threadIdx.x;
    if (i >= NCOL * CC) return;
    int o = i & (CC - 1), j = i >> 11;
    int n = j / WWD, w = j - n * WWD;
    size_t gidx = (size_t)(n * CC + o) * HWP + w;   // h = 0
    float v = fea[gidx];
    out[gidx] = v;                                   // down[0] = x[0]
    g_carry[0][(size_t)j * CC + o] = __float2half(v);
}

// ---------------- launch ----------------
extern "C" void kernel_launch(void* const* d_in, const int* in_sizes, int n_in,
                              void* d_out, int out_size)
{
    const float* fea = (const float*)d_in[0];
    const float* W   = (const float*)d_in[1];
    const float* b   = (const float*)d_in[2];
    float* out = (float*)d_out;

    cudaFuncSetAttribute(step_kernel, cudaFuncAttributeMaxDynamicSharedMemorySize, SMEM_BYTES);

    wprep<<<(CC * CC + 255) / 256, 256>>>(W);
    initk<<<(NCOL * CC + 255) / 256, 256>>>(fea, out);

    int pin = 0;
    for (int i = 0; i < 94; i++) {
        int h = (i < 47) ? (i + 1) : (93 - i);      // forward h=1..47, backward h=46..0
        const float* src = (i < 47) ? fea : out;    // backward residual = down[h] (already in out)
        step_kernel<<<dim3(32, 8), 128, SMEM_BYTES>>>(pin, b, src, out, h);
        pin ^= 1;
    }
}

// round 8
// speedup vs baseline: 1.0917x; 1.0917x over previous
#include <cuda_runtime.h>
#include <cuda_fp16.h>
#include <cstdint>

#define DI __device__ __forceinline__

// problem dims
#define CC   2048
#define WWD  96
#define HWP  4608          // 48*96
#define NCOL 384           // 4*96 GEMM columns

// GEMM tiling
#define BM 64
#define BN 48
#define BK 128
#define KITER (CC/BK)      // 16
#define NST 3
#define AST 136            // padded fp16 row stride (128+8) -> conflict-free ldmatrix
#define A_H (BM*AST)       // 8704 halfs
#define B_H (BN*AST)       // 6528 halfs
#define STG (A_H+B_H)      // 15232 halfs / stage
#define SMEM_BYTES (NST*STG*2)   // 91392 B

// device scratch (static; allocation-rule safe)
__device__ __half g_w[(size_t)CC * CC];            // 8.4 MB, L2-resident
__device__ __half g_carry[2][(size_t)NCOL * CC];   // 2 x 1.5 MB ping-pong

// ---------------- PTX helpers (base sm_103 ISA only) ----------------
DI uint32_t smem_u32(const void* p) {
    uint32_t a;
    asm("{ .reg .u64 t; cvta.to.shared.u64 t, %1; cvt.u32.u64 %0, t; }" : "=r"(a) : "l"(p));
    return a;
}
DI void cp16(uint32_t s, const void* g) {
    asm volatile("cp.async.cg.shared.global [%0], [%1], 16;" :: "r"(s), "l"(g) : "memory");
}
DI void cp_commit() { asm volatile("cp.async.commit_group;" ::: "memory"); }
DI void cp_wait1()  { asm volatile("cp.async.wait_group 1;" ::: "memory"); }

DI void ldsm4(uint32_t a, uint32_t* r) {
    asm volatile("ldmatrix.sync.aligned.m8n8.x4.shared.b16 {%0,%1,%2,%3},[%4];"
        : "=r"(r[0]), "=r"(r[1]), "=r"(r[2]), "=r"(r[3]) : "r"(a));
}
DI void mma16816(float* d, const uint32_t* a, uint32_t b0, uint32_t b1) {
    asm volatile(
        "mma.sync.aligned.m16n8k16.row.col.f32.f16.f16.f32 "
        "{%0,%1,%2,%3},{%4,%5,%6,%7},{%8,%9},{%0,%1,%2,%3};"
        : "+f"(d[0]), "+f"(d[1]), "+f"(d[2]), "+f"(d[3])
        : "r"(a[0]), "r"(a[1]), "r"(a[2]), "r"(a[3]), "r"(b0), "r"(b1));
}

// ---------------- step GEMM kernel ----------------
// D[o][j] = sum_c W[o][c] * carry[j][c];  y = relu(D + b[o]) + src;  out = y; carry' = fp16(y)
__global__ void __launch_bounds__(128, 2)
step_kernel(int pin, const float* __restrict__ bias,
            const float* __restrict__ src, float* __restrict__ out, int h)
{
    extern __shared__ __half sm[];
    uint32_t smb = smem_u32(sm);
    const __half* __restrict__ cin = g_carry[pin];
    __half* __restrict__ cout = g_carry[pin ^ 1];

    const int tid = threadIdx.x, lane = tid & 31, warp = tid >> 5;
    const int mtile = blockIdx.x, ntile = blockIdx.y;
    const __half* gA = g_w + (size_t)(mtile * BM) * CC;
    const __half* gB = cin + (size_t)(ntile * BN) * CC;

    // ---- cp.async stage loader: 1792 16B-units (A:1024, B:768), 14 per thread ----
    auto load_stage = [&](uint32_t base, int kc) {
        #pragma unroll
        for (int i = 0; i < 14; i++) {
            int u = tid + i * 128;
            int isB = (u >= 1024);
            int uu = isB ? u - 1024 : u;
            int r = uu >> 4, ku = uu & 15;
            uint32_t soff = (isB ? A_H : 0) + r * AST + ku * 8;
            const __half* g = (isB ? gB : gA) + (size_t)r * CC + kc + ku * 8;
            cp16(base + soff * 2, g);
        }
    };

    load_stage(smb, 0);                    cp_commit();
    load_stage(smb + STG * 2, BK);         cp_commit();

    // 4 warps: wm = warp (16 rows each), single 48-col N block
    const int wm = warp;
    float acc[6][4];
    #pragma unroll
    for (int ni = 0; ni < 6; ni++)
        #pragma unroll
        for (int e = 0; e < 4; e++) acc[ni][e] = 0.f;

    const int lr = lane & 15;
    const int lh = (lane >> 4) * 8;
    const uint32_t aoff  = (uint32_t)((wm * 16 + lr) * AST + lh) * 2;
    const uint32_t boff0 = (uint32_t)(A_H + lr * AST + lh) * 2;

    int s_cons = 0, s_prod = 2;            // stage indices, no modulo
    #pragma unroll 1
    for (int it = 0; it < KITER; it++) {
        cp_wait1();
        __syncthreads();
        uint32_t base = smb + (uint32_t)(s_cons * STG) * 2;

        // preload kk=0 fragments FIRST (latency head-start)...
        uint32_t a[2][4], b[2][3][4];
        ldsm4(base + aoff, a[0]);
        #pragma unroll
        for (int nb = 0; nb < 3; nb++)
            ldsm4(base + boff0 + (uint32_t)(nb * 16 * AST) * 2, b[0][nb]);

        // ...then issue the next stage's cp.async burst (hidden under LDSM/MMA)
        if (it + NST - 1 < KITER)
            load_stage(smb + (uint32_t)(s_prod * STG) * 2, (it + NST - 1) * BK);
        cp_commit();

        #pragma unroll
        for (int kk = 0; kk < BK / 16; kk++) {
            int cur = kk & 1, nxt = cur ^ 1;
            if (kk + 1 < BK / 16) {
                uint32_t ko = (uint32_t)((kk + 1) * 16) * 2;
                ldsm4(base + aoff + ko, a[nxt]);
                #pragma unroll
                for (int nb = 0; nb < 3; nb++)
                    ldsm4(base + boff0 + (uint32_t)(nb * 16 * AST) * 2 + ko, b[nxt][nb]);
            }
            #pragma unroll
            for (int nb = 0; nb < 3; nb++) {
                mma16816(acc[2 * nb],     a[cur], b[cur][nb][0], b[cur][nb][2]);
                mma16816(acc[2 * nb + 1], a[cur], b[cur][nb][1], b[cur][nb][3]);
            }
        }
        s_cons = (s_cons == NST - 1) ? 0 : s_cons + 1;
        s_prod = (s_prod == NST - 1) ? 0 : s_prod + 1;
    }

    // ---- epilogue ----
    const int g = lane >> 2, cp2 = (lane & 3) * 2;
    const int o0 = mtile * BM + wm * 16;
    float bv0 = bias[o0 + g], bv1 = bias[o0 + g + 8];
    #pragma unroll
    for (int ni = 0; ni < 6; ni++)
        #pragma unroll
        for (int e = 0; e < 4; e++) {
            int o = o0 + g + (e >> 1) * 8;
            int j = ntile * BN + ni * 8 + cp2 + (e & 1);   // global column 0..383
            int n = j / WWD, w = j - n * WWD;
            size_t idx = (size_t)(n * CC + o) * HWP + (size_t)h * WWD + w;
            float v = acc[ni][e] + ((e >> 1) ? bv1 : bv0);
            v = fmaxf(v, 0.f) + src[idx];
            out[idx] = v;
            cout[(size_t)j * CC + o] = __float2half(v);
        }
}

// ---------------- prep kernels ----------------
__global__ void wprep(const float* __restrict__ W) {
    int i = blockIdx.x * 256 + threadIdx.x;
    if (i >= CC * CC) return;
    g_w[i] = __float2half(W[(size_t)i * 9 + 4]);   // center tap of KH=9
}

__global__ void initk(const float* __restrict__ fea, float* __restrict__ out) {
    int i = blockIdx.x * 256 + threadIdx.x;
    if (i >= NCOL * CC) return;
    int o = i & (CC - 1), j = i >> 11;
    int n = j / WWD, w = j - n * WWD;
    size_t gidx = (size_t)(n * CC + o) * HWP + w;   // h = 0
    float v = fea[gidx];
    out[gidx] = v;                                   // down[0] = x[0]
    g_carry[0][(size_t)j * CC + o] = __float2half(v);
}

// ---------------- launch ----------------
extern "C" void kernel_launch(void* const* d_in, const int* in_sizes, int n_in,
                              void* d_out, int out_size)
{
    const float* fea = (const float*)d_in[0];
    const float* W   = (const float*)d_in[1];
    const float* b   = (const float*)d_in[2];
    float* out = (float*)d_out;

    cudaFuncSetAttribute(step_kernel, cudaFuncAttributeMaxDynamicSharedMemorySize, SMEM_BYTES);

    wprep<<<(CC * CC + 255) / 256, 256>>>(W);
    initk<<<(NCOL * CC + 255) / 256, 256>>>(fea, out);

    int pin = 0;
    for (int i = 0; i < 94; i++) {
        int h = (i < 47) ? (i + 1) : (93 - i);      // forward h=1..47, backward h=46..0
        const float* src = (i < 47) ? fea : out;    // backward residual = down[h] (already in out)
        step_kernel<<<dim3(32, 8), 128, SMEM_BYTES>>>(pin, b, src, out, h);
        pin ^= 1;
    }
}

// round 9
// speedup vs baseline: 1.3536x; 1.2399x over previous
#include <cuda_runtime.h>
#include <cuda_fp16.h>
#include <cstdint>

#define DI __device__ __forceinline__

// problem dims
#define CC   2048
#define WWD  96
#define HWP  4608          // 48*96
#define NCOL 384           // 4*96 GEMM columns

// GEMM tiling
#define BM 64
#define BN 48
#define BK 128
#define KITER (CC/BK)      // 16
#define NST 3
#define AST 136            // padded fp16 row stride (128+8) -> conflict-free ldmatrix
#define A_H (BM*AST)       // 8704 halfs
#define B_H (BN*AST)       // 6528 halfs
#define STG (A_H+B_H)      // 15232 halfs / stage
#define SMEM_BYTES (NST*STG*2)   // 91392 B
#define TPAD 72            // transpose tile stride (64 + 8 halfs)

// device scratch (static; allocation-rule safe)
__device__ __half g_w[(size_t)CC * CC];            // 8.4 MB, L2-resident
__device__ __half g_carry[2][(size_t)NCOL * CC];   // 2 x 1.5 MB ping-pong

// ---------------- PTX helpers (base sm_103 ISA only) ----------------
DI uint32_t smem_u32(const void* p) {
    uint32_t a;
    asm("{ .reg .u64 t; cvta.to.shared.u64 t, %1; cvt.u32.u64 %0, t; }" : "=r"(a) : "l"(p));
    return a;
}
DI void cp16(uint32_t s, const void* g) {
    asm volatile("cp.async.cg.shared.global [%0], [%1], 16;" :: "r"(s), "l"(g) : "memory");
}
DI void cp_commit() { asm volatile("cp.async.commit_group;" ::: "memory"); }
DI void cp_wait1()  { asm volatile("cp.async.wait_group 1;" ::: "memory"); }

DI void ldsm4(uint32_t a, uint32_t* r) {
    asm volatile("ldmatrix.sync.aligned.m8n8.x4.shared.b16 {%0,%1,%2,%3},[%4];"
        : "=r"(r[0]), "=r"(r[1]), "=r"(r[2]), "=r"(r[3]) : "r"(a));
}
DI void mma16816(float* d, const uint32_t* a, uint32_t b0, uint32_t b1) {
    asm volatile(
        "mma.sync.aligned.m16n8k16.row.col.f32.f16.f16.f32 "
        "{%0,%1,%2,%3},{%4,%5,%6,%7},{%8,%9},{%0,%1,%2,%3};"
        : "+f"(d[0]), "+f"(d[1]), "+f"(d[2]), "+f"(d[3])
        : "r"(a[0]), "r"(a[1]), "r"(a[2]), "r"(a[3]), "r"(b0), "r"(b1));
}

// ---------------- step GEMM kernel ----------------
// D[o][j] = sum_c W[o][c] * carry[j][c];  y = relu(D + b[o]) + src;  out = y; carry' = fp16(y)
__global__ void __launch_bounds__(128, 2)
step_kernel(int pin, const float* __restrict__ bias,
            const float* __restrict__ src, float* __restrict__ out, int h)
{
    extern __shared__ __half sm[];
    uint32_t smb = smem_u32(sm);
    const __half* __restrict__ cin = g_carry[pin];
    __half* __restrict__ cout = g_carry[pin ^ 1];

    const int tid = threadIdx.x, lane = tid & 31, warp = tid >> 5;
    const int mtile = blockIdx.x, ntile = blockIdx.y;
    const __half* gA = g_w + (size_t)(mtile * BM) * CC;
    const __half* gB = cin + (size_t)(ntile * BN) * CC;

    // one 16B unit: u in [0,1792): A units [0,1024), B units [1024,1792)
    auto load_unit = [&](uint32_t base, int kc, int u) {
        int isB = (u >= 1024);
        int uu = isB ? u - 1024 : u;
        int r = uu >> 4, ku = uu & 15;
        uint32_t soff = (isB ? A_H : 0) + r * AST + ku * 8;
        const __half* g = (isB ? gB : gA) + (size_t)r * CC + kc + ku * 8;
        cp16(base + soff * 2, g);
    };
    auto load_stage = [&](uint32_t base, int kc) {
        #pragma unroll
        for (int i = 0; i < 14; i++) load_unit(base, kc, tid + i * 128);
    };

    load_stage(smb, 0);                    cp_commit();
    load_stage(smb + STG * 2, BK);         cp_commit();

    // 4 warps: wm = warp (16 rows each), single 48-col N block
    const int wm = warp;
    float acc[6][4];
    #pragma unroll
    for (int ni = 0; ni < 6; ni++)
        #pragma unroll
        for (int e = 0; e < 4; e++) acc[ni][e] = 0.f;

    const int lr = lane & 15;
    const int lh = (lane >> 4) * 8;
    const uint32_t aoff  = (uint32_t)((wm * 16 + lr) * AST + lh) * 2;
    const uint32_t boff0 = (uint32_t)(A_H + lr * AST + lh) * 2;

    int s_cons = 0, s_prod = 2;            // stage indices, no modulo
    #pragma unroll 1
    for (int it = 0; it < KITER; it++) {
        cp_wait1();
        __syncthreads();
        uint32_t base = smb + (uint32_t)(s_cons * STG) * 2;

        // preload kk=0 fragments first (latency head-start)
        uint32_t a[2][4], b[2][3][4];
        ldsm4(base + aoff, a[0]);
        #pragma unroll
        for (int nb = 0; nb < 3; nb++)
            ldsm4(base + boff0 + (uint32_t)(nb * 16 * AST) * 2, b[0][nb]);

        const int pf = (it + NST - 1 < KITER);
        uint32_t pbase = smb + (uint32_t)(s_prod * STG) * 2;
        const int pkc = (it + NST - 1) * BK;

        #pragma unroll
        for (int kk = 0; kk < BK / 16; kk++) {
            int cur = kk & 1, nxt = cur ^ 1;
            if (kk + 1 < BK / 16) {
                uint32_t ko = (uint32_t)((kk + 1) * 16) * 2;
                ldsm4(base + aoff + ko, a[nxt]);
                #pragma unroll
                for (int nb = 0; nb < 3; nb++)
                    ldsm4(base + boff0 + (uint32_t)(nb * 16 * AST) * 2 + ko, b[nxt][nb]);
                // spread next-stage cp.async: 2 units per thread per k-block (7 blocks x 256 = 1792)
                if (pf) {
                    load_unit(pbase, pkc, kk * 256 + tid);
                    load_unit(pbase, pkc, kk * 256 + 128 + tid);
                }
            }
            #pragma unroll
            for (int nb = 0; nb < 3; nb++) {
                mma16816(acc[2 * nb],     a[cur], b[cur][nb][0], b[cur][nb][2]);
                mma16816(acc[2 * nb + 1], a[cur], b[cur][nb][1], b[cur][nb][3]);
            }
        }
        cp_commit();   // empty group when pf==0 (completes immediately)
        s_cons = (s_cons == NST - 1) ? 0 : s_cons + 1;
        s_prod = (s_prod == NST - 1) ? 0 : s_prod + 1;
    }

    // ---- epilogue ----
    __syncthreads();   // all smem stage reads complete; reuse stage 0 as transpose tile
    const int g = lane >> 2, cp2 = (lane & 3) * 2;
    const int o0 = mtile * BM + wm * 16;
    float bv0 = bias[o0 + g], bv1 = bias[o0 + g + 8];
    #pragma unroll
    for (int ni = 0; ni < 6; ni++)
        #pragma unroll
        for (int e = 0; e < 4; e++) {
            int o_l = wm * 16 + g + (e >> 1) * 8;          // 0..63 within BM
            int j_l = ni * 8 + cp2 + (e & 1);              // 0..47 within BN
            int o = mtile * BM + o_l;
            int j = ntile * BN + j_l;
            int n = j / WWD, w = j - n * WWD;
            size_t idx = (size_t)(n * CC + o) * HWP + (size_t)h * WWD + w;
            float v = acc[ni][e] + ((e >> 1) ? bv1 : bv0);
            v = fmaxf(v, 0.f) + src[idx];
            out[idx] = v;
            sm[j_l * TPAD + o_l] = __float2half(v);        // smem transpose staging
        }
    __syncthreads();
    // coalesced carry writes: 48 rows x 64 halfs = 384 16B segments, 3 per thread
    #pragma unroll
    for (int t2 = 0; t2 < 3; t2++) {
        int seg = tid + t2 * 128;
        int j_l = seg >> 3, os = (seg & 7) * 8;
        uint4 val = *reinterpret_cast<const uint4*>(&sm[j_l * TPAD + os]);
        *reinterpret_cast<uint4*>(&cout[(size_t)(ntile * BN + j_l) * CC + mtile * BM + os]) = val;
    }
}

// ---------------- prep kernels ----------------
__global__ void wprep(const float* __restrict__ W) {
    int i = blockIdx.x * 256 + threadIdx.x;
    if (i >= CC * CC) return;
    g_w[i] = __float2half(W[(size_t)i * 9 + 4]);   // center tap of KH=9
}

__global__ void initk(const float* __restrict__ fea, float* __restrict__ out) {
    int i = blockIdx.x * 256 + threadIdx.x;
    if (i >= NCOL * CC) return;
    int o = i & (CC - 1), j = i >> 11;
    int n = j / WWD, w = j - n * WWD;
    size_t gidx = (size_t)(n * CC + o) * HWP + w;   // h = 0
    float v = fea[gidx];
    out[gidx] = v;                                   // down[0] = x[0]
    g_carry[0][(size_t)j * CC + o] = __float2half(v);
}

// ---------------- launch ----------------
extern "C" void kernel_launch(void* const* d_in, const int* in_sizes, int n_in,
                              void* d_out, int out_size)
{
    const float* fea = (const float*)d_in[0];
    const float* W   = (const float*)d_in[1];
    const float* b   = (const float*)d_in[2];
    float* out = (float*)d_out;

    cudaFuncSetAttribute(step_kernel, cudaFuncAttributeMaxDynamicSharedMemorySize, SMEM_BYTES);

    wprep<<<(CC * CC + 255) / 256, 256>>>(W);
    initk<<<(NCOL * CC + 255) / 256, 256>>>(fea, out);

    int pin = 0;
    for (int i = 0; i < 94; i++) {
        int h = (i < 47) ? (i + 1) : (93 - i);      // forward h=1..47, backward h=46..0
        const float* src = (i < 47) ? fea : out;    // backward residual = down[h] (already in out)
        step_kernel<<<dim3(32, 8), 128, SMEM_BYTES>>>(pin, b, src, out, h);
        pin ^= 1;
    }
}